// round 6
// baseline (speedup 1.0000x reference)
#include <cuda_runtime.h>

// DTM (distance-to-measure) on a 64x64 integer grid.
// Per (b,c) slice: bound = 0.05 * sum(w). Per point p: walk grid points in
// order of increasing squared distance, accumulate weight until crossing
// bound, output sqrt((sum_{d<d*} d^2 w + d*^2 (bound - cum_before)) / bound).
// Weights quantized to q = floor(w * 65535): we solve that perturbed problem
// EXACTLY in integers (result is scale-invariant in w, so rel err ~1e-5).
// With B = S/20 (S = sum of q): k = first prefix with 20*cum >= S, and
// dtm = sqrt(num / S), num = 20*sum_{i<k} d2_i q_i + d2_k*(S - 20 cum_{k-1}).

#define HW 4096
#define NSLICE 12
#define NOFF 16129            // (dy,dx) in [-63,63]^2
#define NMAIN 16128           // 126 batches of 128; 1 epilogue entry
#define PITCH 191
#define SMROWS 190
#define SMCELLS (SMROWS * PITCH)  // 36290 u16 cells
#define SMWORDS (SMCELLS / 2)     // 18145 u32 words
#define SMBYTES (SMCELLS * 2)     // 72580 bytes
#define QS 65535.0f

// entry: d2 << 16 | ((dy*PITCH + dx + 32768) & 0xFFFF)
__device__ __align__(16) unsigned g_tab[NOFF];

// ---- build: 4 lanes per offset compute its sorted rank in closed form ----

__global__ void __launch_bounds__(256) k_build() {
    int gid = blockIdx.x * 256 + threadIdx.x;
    int i = gid >> 2;
    int q = gid & 3;
    int dy = i / 127 - 63;
    int dx = i % 127 - 63;
    int d2 = dy * dy + dx * dx;
    int pos = 0;
    if (i < NOFF) {
        for (int a = q; a <= 63; a += 4) {  // +-a handled together
            int na = d2 - a * a;
            if (na < 0) break;
            int s = (int)sqrtf((float)na);  // exact floor at these magnitudes
            bool perf = (s * s == na);
            if (na > 0) {                   // # of b with b^2 < na, |b|<=63
                int tt = perf ? s - 1 : s;
                if (tt > 63) tt = 63;
                int cb = 2 * tt + 1;
                pos += (a == 0) ? cb : 2 * cb;
            }
            if (perf && s <= 63) {          // ties b = +-s, lex (a,b) order
                if (a < dy) pos += (s == 0) ? 1 : 2;
                else if (a == dy) {
                    if (-s < dx) pos++;
                    if (s != 0 && s < dx) pos++;
                }
                if (a != 0) {
                    int aa = -a;
                    if (aa < dy) pos += (s == 0) ? 1 : 2;
                    else if (aa == dy) {
                        if (-s < dx) pos++;
                        if (s != 0 && s < dx) pos++;
                    }
                }
            }
        }
    }
    pos += __shfl_xor_sync(~0u, pos, 1);
    pos += __shfl_xor_sync(~0u, pos, 2);
    if (q == 0 && i < NOFF) {
        g_tab[pos] = ((unsigned)d2 << 16) |
                     (unsigned)((dy * PITCH + dx + 32768) & 0xFFFF);
    }
}

// ---- main: one warp per point, 128 sorted entries per step (4/lane) ----

__global__ void __launch_bounds__(1024, 2)
k_main(const float* __restrict__ x, float* __restrict__ out) {
    extern __shared__ unsigned short swq[];  // padded 190x191 u16 weights
    __shared__ int sred[32];
    __shared__ int sS;

    int t = threadIdx.x;
    int slice = blockIdx.x >> 7;   // 128 point-groups of 32 per slice
    int pg = blockIdx.x & 127;
    const float4* src4 = (const float4*)(x + slice * HW);

    // zero the padded array (u32 writes)
    unsigned* swq32 = (unsigned*)swq;
    for (int i = t; i < SMWORDS; i += 1024) swq32[i] = 0;
    __syncthreads();

    // load + quantize 4 contiguous cells per thread (never crosses a row)
    float4 v = src4[t];
    int cell = t * 4;
    int a = ((cell >> 6) + 63) * PITCH + (cell & 63) + 63;
    int q0 = (int)(v.x * QS), q1 = (int)(v.y * QS);
    int q2 = (int)(v.z * QS), q3 = (int)(v.w * QS);
    swq[a + 0] = (unsigned short)q0;
    swq[a + 1] = (unsigned short)q1;
    swq[a + 2] = (unsigned short)q2;
    swq[a + 3] = (unsigned short)q3;
    int ls = (q0 + q1) + (q2 + q3);
#pragma unroll
    for (int o = 16; o; o >>= 1) ls += __shfl_xor_sync(~0u, ls, o);
    if ((t & 31) == 0) sred[t >> 5] = ls;
    __syncthreads();
    if (t == 0) {
        int S = 0;
#pragma unroll
        for (int k = 0; k < 32; k++) S += sred[k];
        sS = S;
    }
    __syncthreads();
    int S = sS;
    int Bc = (S + 19) / 20;  // crossing: first integer cum >= ceil(S/20)

    int w = t >> 5;
    int lane = t & 31;
    int p = (pg << 5) + w;
    int row = p >> 6;
    int col = p & 63;
    int pb2 = (row + 63) * PITCH + (col + 63) - 32768;  // bias folded in

    int cum = 0;                  // warp-uniform exact integer running sum
    unsigned long long acc = 0;   // per-lane distributed sum of d2*q
    unsigned long long num = 0;
    int crossed = 0;

    const uint4* tp = (const uint4*)g_tab;  // uint4 = 4 entries

    for (int base = 0; base < NMAIN; base += 128) {
        uint4 c = __ldg(tp + (base >> 2) + lane);
        int i0 = pb2 + (int)(c.x & 0xFFFFu);
        int i1 = pb2 + (int)(c.y & 0xFFFFu);
        int i2 = pb2 + (int)(c.z & 0xFFFFu);
        int i3 = pb2 + (int)(c.w & 0xFFFFu);
        int d0 = (int)(c.x >> 16), d1 = (int)(c.y >> 16);
        int d2v = (int)(c.z >> 16), d3 = (int)(c.w >> 16);
        int w0 = swq[i0], w1 = swq[i1], w2 = swq[i2], w3 = swq[i3];

        int mi = (w0 + w1) + (w2 + w3);
        int tot = __reduce_add_sync(~0u, mi);  // all lanes get the sum

        if (cum + tot >= Bc) {  // warp-uniform, exact
            // ordered resolve (once per point)
            int s = mi;
#pragma unroll
            for (int o = 1; o < 32; o <<= 1) {
                int u = __shfl_up_sync(~0u, s, o);
                if (lane >= o) s += u;
            }
            int b0 = cum + s - mi;  // exact cum before this lane's entries
            int e1 = b0 + w0, e2 = e1 + w1, e3 = e2 + w2, e4 = e3 + w3;
            unsigned m = __ballot_sync(~0u, e4 >= Bc);  // bit31 guaranteed
            int fl = __ffs(m) - 1;
            unsigned long long part = 0;
            if (lane < fl) {
                acc += (unsigned long long)(unsigned)(d0 * w0);
                acc += (unsigned long long)(unsigned)(d1 * w1);
                acc += (unsigned long long)(unsigned)(d2v * w2);
                acc += (unsigned long long)(unsigned)(d3 * w3);
            } else if (lane == fl) {
                if (e1 >= Bc) {
                    part = (unsigned long long)d0 * (unsigned)(S - 20 * b0);
                } else {
                    acc += (unsigned long long)(unsigned)(d0 * w0);
                    if (e2 >= Bc) {
                        part = (unsigned long long)d1 * (unsigned)(S - 20 * e1);
                    } else {
                        acc += (unsigned long long)(unsigned)(d1 * w1);
                        if (e3 >= Bc) {
                            part = (unsigned long long)d2v *
                                   (unsigned)(S - 20 * e2);
                        } else {
                            acc += (unsigned long long)(unsigned)(d2v * w2);
                            part = (unsigned long long)d3 *
                                   (unsigned)(S - 20 * e3);
                        }
                    }
                }
            }
            num = acc * 20ull + part;
            crossed = 1;
            break;  // warp-uniform exit
        }
        cum += tot;
        acc += (unsigned long long)(unsigned)(d0 * w0);
        acc += (unsigned long long)(unsigned)(d1 * w1);
        acc += (unsigned long long)(unsigned)(d2v * w2);
        acc += (unsigned long long)(unsigned)(d3 * w3);
    }

    if (!crossed) {  // essentially never: resolve on the single last entry
        unsigned e = g_tab[NMAIN];
        int dd = (int)(e >> 16);
        int rem = S - 20 * cum;
        if (rem < 0) rem = 0;
        num = acc * 20ull +
              (lane == 0 ? (unsigned long long)dd * (unsigned)rem : 0ull);
    }

#pragma unroll
    for (int o = 16; o; o >>= 1) num += __shfl_xor_sync(~0u, num, o);
    if (lane == 0)
        out[slice * HW + p] = (float)sqrt((double)num / (double)S);
}

extern "C" void kernel_launch(void* const* d_in, const int* in_sizes, int n_in,
                              void* d_out, int out_size) {
    const float* x = (const float*)d_in[0];
    float* out = (float*)d_out;

    cudaFuncSetAttribute(k_main, cudaFuncAttributeMaxDynamicSharedMemorySize,
                         SMBYTES);
    k_build<<<(NOFF * 4 + 255) / 256, 256>>>();
    k_main<<<NSLICE * 128, 1024, SMBYTES>>>(x, out);
}